// round 5
// baseline (speedup 1.0000x reference)
#include <cuda_runtime.h>
#include <cuda_bf16.h>

// NaiveVisCache: per-ray cubemap-face + voxel index, gather numer/denom, divide.
// numer/denom: [128,128,128,6] int32 (~50MB each -> mostly L2-resident).
// 4 rays/thread via float4 loads (coalesced), batch all 8 gather LDGs (MLP=8).
//
// NUMERICS: the reference's face test compares sqdirs = viewdirs / inf_norm
// against +/-1.0, and the max component's ratio sits exactly at the rounding
// boundary. Measured fall-through rate of the reference is 0.139, which equals
// the analytic P( RN(x*RN(1/x)) < 1 ) = (1 - 1/(2 ln 2))/2 = 0.139 for
// log-uniform mantissas. => the reference multiplies by the CORRECTLY-ROUNDED
// RECIPROCAL (XLA's div-by-broadcast-scalar rewrite). Replicate bit-for-bit
// with __frcp_rn + multiply.

#define VGRID 128

__device__ __forceinline__ int coord_clip(float o) {
    // (o/2 + 0.5) * 127, clip [0,127], truncate (matches jnp astype).
    // o*0.5 is exact, so FMA contraction is bit-identical to mul+add.
    float t = (o * 0.5f + 0.5f) * (float)(VGRID - 1);
    t = fminf(fmaxf(t, 0.0f), (float)(VGRID - 1));
    return (int)t;
}

__device__ __forceinline__ int ray_index(float o0, float o1, float o2,
                                         float d0, float d1, float d2) {
    float inf = fmaxf(fabsf(d0), fmaxf(fabsf(d1), fabsf(d2)));
    // Reference: sqdirs = viewdirs * RN(1/inf_norm). Bit-exact replication.
    float rinf = __frcp_rn(inf);
    float sa = d0 * rinf;
    float sb = d1 * rinf;
    float sc = d2 * rinf;
    // Reference loop: last true condition wins -> sequential overwrites;
    // if the max ratio rounds to 1-1ulp, face stays 0 (fall-through).
    int f = 0;
    if (sa >=  1.0f) f = 0;
    if (sa <= -1.0f) f = 1;
    if (sb >=  1.0f) f = 2;
    if (sb <= -1.0f) f = 3;
    if (sc >=  1.0f) f = 4;
    if (sc <= -1.0f) f = 5;
    int i = coord_clip(o0);
    int j = coord_clip(o1);
    int k = coord_clip(o2);
    return (((i * VGRID + j) * VGRID + k) * 6) + f;
}

__global__ void __launch_bounds__(256)
vis_cache_kernel(const float4* __restrict__ o4,
                 const float4* __restrict__ v4,
                 const int*    __restrict__ numer,
                 const int*    __restrict__ denom,
                 float4*       __restrict__ out,
                 int nquads) {
    int t = blockIdx.x * blockDim.x + threadIdx.x;
    if (t >= nquads) return;

    // 4 rays = 12 floats = 3 float4 per tensor
    float4 oa = o4[3 * t + 0];
    float4 ob = o4[3 * t + 1];
    float4 oc = o4[3 * t + 2];
    float4 va = v4[3 * t + 0];
    float4 vb = v4[3 * t + 1];
    float4 vc = v4[3 * t + 2];

    int idx0 = ray_index(oa.x, oa.y, oa.z, va.x, va.y, va.z);
    int idx1 = ray_index(oa.w, ob.x, ob.y, va.w, vb.x, vb.y);
    int idx2 = ray_index(ob.z, ob.w, oc.x, vb.z, vb.w, vc.x);
    int idx3 = ray_index(oc.y, oc.z, oc.w, vc.y, vc.z, vc.w);

    // Batch all 8 gathers before consuming: MLP=8 per thread.
    int n0 = __ldg(numer + idx0);
    int n1 = __ldg(numer + idx1);
    int n2 = __ldg(numer + idx2);
    int n3 = __ldg(numer + idx3);
    int d0 = __ldg(denom + idx0);
    int d1 = __ldg(denom + idx1);
    int d2 = __ldg(denom + idx2);
    int d3 = __ldg(denom + idx3);

    float4 r;
    r.x = __fdiv_rn((float)n0, (float)d0);
    r.y = __fdiv_rn((float)n1, (float)d1);
    r.z = __fdiv_rn((float)n2, (float)d2);
    r.w = __fdiv_rn((float)n3, (float)d3);
    out[t] = r;
}

__global__ void __launch_bounds__(256)
vis_cache_tail(const float* __restrict__ origins,
               const float* __restrict__ dirs,
               const int*   __restrict__ numer,
               const int*   __restrict__ denom,
               float*       __restrict__ out,
               int start, int nrays) {
    int r = start + blockIdx.x * blockDim.x + threadIdx.x;
    if (r >= nrays) return;
    int idx = ray_index(origins[3 * r], origins[3 * r + 1], origins[3 * r + 2],
                        dirs[3 * r],    dirs[3 * r + 1],    dirs[3 * r + 2]);
    out[r] = __fdiv_rn((float)__ldg(numer + idx), (float)__ldg(denom + idx));
}

extern "C" void kernel_launch(void* const* d_in, const int* in_sizes, int n_in,
                              void* d_out, int out_size) {
    const float* origins = (const float*)d_in[0];  // [B,3] f32
    const float* dirs    = (const float*)d_in[1];  // [B,3] f32
    const int*   numer   = (const int*)d_in[2];    // [128,128,128,6] i32
    const int*   denom   = (const int*)d_in[3];    // [128,128,128,6] i32
    float* out = (float*)d_out;

    int nrays  = in_sizes[0] / 3;
    int nquads = nrays >> 2;

    if (nquads > 0) {
        int threads = 256;
        int blocks = (nquads + threads - 1) / threads;
        vis_cache_kernel<<<blocks, threads>>>(
            (const float4*)origins, (const float4*)dirs,
            numer, denom, (float4*)out, nquads);
    }
    int tail_start = nquads << 2;
    int tail = nrays - tail_start;
    if (tail > 0) {
        vis_cache_tail<<<(tail + 255) / 256, 256>>>(
            origins, dirs, numer, denom, out, tail_start, nrays);
    }
}

// round 7
// speedup vs baseline: 1.1283x; 1.1283x over previous
#include <cuda_runtime.h>
#include <cuda_bf16.h>

// NaiveVisCache: per-ray cubemap-face + voxel index, gather numer/denom, divide.
// R6: L2 eviction-priority segregation, fixed encoding.
//   - streams (origins/dirs, out): __ldcs/__stcs (.cs streaming, all widths ok)
//   - table gathers: createpolicy.fractional.L2::evict_last (1.0) +
//     ld.global.nc.L2::cache_hint  (policy-register form; the direct
//     .L2::evict_last modifier is only legal on 256-bit loads per ptxas).
// Goal: keep the 100MB numer+denom working set resident in the 126MB L2 so
// the ~268MB of random 32B gather sectors stop going to DRAM; streams
// (~113MB) remain the only compulsory DRAM traffic.

#define VGRID 128

__device__ __forceinline__ unsigned long long make_evict_last_policy() {
    unsigned long long pol;
    asm("createpolicy.fractional.L2::evict_last.b64 %0, 1.0;" : "=l"(pol));
    return pol;
}

__device__ __forceinline__ int ldg_table(const int* p, unsigned long long pol) {
    int v;
    asm volatile("ld.global.nc.L2::cache_hint.s32 %0, [%1], %2;"
                 : "=r"(v) : "l"(p), "l"(pol));
    return v;
}

__device__ __forceinline__ int coord_clip(float o) {
    // (o/2 + 0.5) * 127, clip [0,127], truncate (matches jnp astype).
    float t = (o * 0.5f + 0.5f) * (float)(VGRID - 1);
    t = fminf(fmaxf(t, 0.0f), (float)(VGRID - 1));
    return (int)t;
}

__device__ __forceinline__ int ray_index(float o0, float o1, float o2,
                                         float d0, float d1, float d2) {
    float inf = fmaxf(fabsf(d0), fmaxf(fabsf(d1), fabsf(d2)));
    // Reference: sqdirs = viewdirs * RN(1/inf_norm). Bit-exact (R4: rel_err 0).
    float rinf = __frcp_rn(inf);
    float sa = d0 * rinf;
    float sb = d1 * rinf;
    float sc = d2 * rinf;
    int f = 0;
    if (sa >=  1.0f) f = 0;
    if (sa <= -1.0f) f = 1;
    if (sb >=  1.0f) f = 2;
    if (sb <= -1.0f) f = 3;
    if (sc >=  1.0f) f = 4;
    if (sc <= -1.0f) f = 5;
    int i = coord_clip(o0);
    int j = coord_clip(o1);
    int k = coord_clip(o2);
    return (((i * VGRID + j) * VGRID + k) * 6) + f;
}

__global__ void __launch_bounds__(256)
vis_cache_kernel(const float4* __restrict__ o4,
                 const float4* __restrict__ v4,
                 const int*    __restrict__ numer,
                 const int*    __restrict__ denom,
                 float4*       __restrict__ out,
                 int nquads) {
    int t = blockIdx.x * blockDim.x + threadIdx.x;
    if (t >= nquads) return;

    unsigned long long pol = make_evict_last_policy();

    // 4 rays = 12 floats = 3 float4 per tensor; streaming loads (.cs).
    float4 oa = __ldcs(o4 + 3 * t + 0);
    float4 ob = __ldcs(o4 + 3 * t + 1);
    float4 oc = __ldcs(o4 + 3 * t + 2);
    float4 va = __ldcs(v4 + 3 * t + 0);
    float4 vb = __ldcs(v4 + 3 * t + 1);
    float4 vc = __ldcs(v4 + 3 * t + 2);

    int idx0 = ray_index(oa.x, oa.y, oa.z, va.x, va.y, va.z);
    int idx1 = ray_index(oa.w, ob.x, ob.y, va.w, vb.x, vb.y);
    int idx2 = ray_index(ob.z, ob.w, oc.x, vb.z, vb.w, vc.x);
    int idx3 = ray_index(oc.y, oc.z, oc.w, vc.y, vc.z, vc.w);

    // Batch all 8 gathers (MLP=8); pin table sectors via evict_last policy.
    int n0 = ldg_table(numer + idx0, pol);
    int n1 = ldg_table(numer + idx1, pol);
    int n2 = ldg_table(numer + idx2, pol);
    int n3 = ldg_table(numer + idx3, pol);
    int d0 = ldg_table(denom + idx0, pol);
    int d1 = ldg_table(denom + idx1, pol);
    int d2 = ldg_table(denom + idx2, pol);
    int d3 = ldg_table(denom + idx3, pol);

    float4 r;
    r.x = __fdiv_rn((float)n0, (float)d0);
    r.y = __fdiv_rn((float)n1, (float)d1);
    r.z = __fdiv_rn((float)n2, (float)d2);
    r.w = __fdiv_rn((float)n3, (float)d3);
    __stcs(out + t, r);
}

__global__ void __launch_bounds__(256)
vis_cache_tail(const float* __restrict__ origins,
               const float* __restrict__ dirs,
               const int*   __restrict__ numer,
               const int*   __restrict__ denom,
               float*       __restrict__ out,
               int start, int nrays) {
    int r = start + blockIdx.x * blockDim.x + threadIdx.x;
    if (r >= nrays) return;
    int idx = ray_index(origins[3 * r], origins[3 * r + 1], origins[3 * r + 2],
                        dirs[3 * r],    dirs[3 * r + 1],    dirs[3 * r + 2]);
    out[r] = __fdiv_rn((float)__ldg(numer + idx), (float)__ldg(denom + idx));
}

extern "C" void kernel_launch(void* const* d_in, const int* in_sizes, int n_in,
                              void* d_out, int out_size) {
    const float* origins = (const float*)d_in[0];  // [B,3] f32
    const float* dirs    = (const float*)d_in[1];  // [B,3] f32
    const int*   numer   = (const int*)d_in[2];    // [128,128,128,6] i32
    const int*   denom   = (const int*)d_in[3];    // [128,128,128,6] i32
    float* out = (float*)d_out;

    int nrays  = in_sizes[0] / 3;
    int nquads = nrays >> 2;

    if (nquads > 0) {
        int threads = 256;
        int blocks = (nquads + threads - 1) / threads;
        vis_cache_kernel<<<blocks, threads>>>(
            (const float4*)origins, (const float4*)dirs,
            numer, denom, (float4*)out, nquads);
    }
    int tail_start = nquads << 2;
    int tail = nrays - tail_start;
    if (tail > 0) {
        vis_cache_tail<<<(tail + 255) / 256, 256>>>(
            origins, dirs, numer, denom, out, tail_start, nrays);
    }
}

// round 8
// speedup vs baseline: 1.4190x; 1.2577x over previous
#include <cuda_runtime.h>
#include <cuda_bf16.h>

// NaiveVisCache R7: two-phase.
//  Phase 1 (streaming): fuse numer/denom into one 50MB ratio table
//      g_ratio[i] = fdiv_rn(n[i], d[i])
//    stored with an L2::evict_last policy so the whole table is L2-resident
//    when phase 2 runs (50MB << 126MB L2).
//  Phase 2 (gather): one 4B gather per ray (was two) from the L2-hot ratio
//    table; streams use .cs. Halves gather sector traffic AND converts the
//    remaining gathers from DRAM misses into L2 hits.
// Numerics: fdiv_rn(n,d) matched the reference bit-exact in R4/R6 (rel_err=0),
// face/index path unchanged (rcp.rn + mul, verified exact).

#define VGRID 128
#define TABLE_N (VGRID * VGRID * VGRID * 6)   // 12,582,912 entries

__device__ float g_ratio[TABLE_N];            // 50.3MB static scratch

__device__ __forceinline__ unsigned long long evict_last_policy() {
    unsigned long long pol;
    asm("createpolicy.fractional.L2::evict_last.b64 %0, 1.0;" : "=l"(pol));
    return pol;
}

// ---------------- Phase 1: fuse tables ----------------
__global__ void __launch_bounds__(256)
fuse_ratio_kernel(const int4* __restrict__ numer4,
                  const int4* __restrict__ denom4,
                  int nvec) {
    int t = blockIdx.x * blockDim.x + threadIdx.x;
    if (t >= nvec) return;
    unsigned long long pol = evict_last_policy();

    int4 n = __ldcs(numer4 + t);   // touch-once streams
    int4 d = __ldcs(denom4 + t);
    float4 r;
    r.x = __fdiv_rn((float)n.x, (float)d.x);
    r.y = __fdiv_rn((float)n.y, (float)d.y);
    r.z = __fdiv_rn((float)n.z, (float)d.z);
    r.w = __fdiv_rn((float)n.w, (float)d.w);
    // Store with evict_last so the ratio table is L2-resident for phase 2.
    asm volatile("st.global.L2::cache_hint.v4.f32 [%0], {%1,%2,%3,%4}, %5;"
                 :: "l"(g_ratio + 4 * (size_t)t),
                    "f"(r.x), "f"(r.y), "f"(r.z), "f"(r.w), "l"(pol));
}

// ---------------- index math (bit-exact vs reference) ----------------
__device__ __forceinline__ int coord_clip(float o) {
    float t = (o * 0.5f + 0.5f) * (float)(VGRID - 1);
    t = fminf(fmaxf(t, 0.0f), (float)(VGRID - 1));
    return (int)t;
}

__device__ __forceinline__ int ray_index(float o0, float o1, float o2,
                                         float d0, float d1, float d2) {
    float inf = fmaxf(fabsf(d0), fmaxf(fabsf(d1), fabsf(d2)));
    // Reference: sqdirs = viewdirs * RN(1/inf_norm) (verified bit-exact, R4).
    float rinf = __frcp_rn(inf);
    float sa = d0 * rinf;
    float sb = d1 * rinf;
    float sc = d2 * rinf;
    int f = 0;
    if (sa >=  1.0f) f = 0;
    if (sa <= -1.0f) f = 1;
    if (sb >=  1.0f) f = 2;
    if (sb <= -1.0f) f = 3;
    if (sc >=  1.0f) f = 4;
    if (sc <= -1.0f) f = 5;
    int i = coord_clip(o0);
    int j = coord_clip(o1);
    int k = coord_clip(o2);
    return (((i * VGRID + j) * VGRID + k) * 6) + f;
}

// ---------------- Phase 2: gather ----------------
__global__ void __launch_bounds__(256)
vis_cache_kernel(const float4* __restrict__ o4,
                 const float4* __restrict__ v4,
                 float4*       __restrict__ out,
                 int nquads) {
    int t = blockIdx.x * blockDim.x + threadIdx.x;
    if (t >= nquads) return;
    unsigned long long pol = evict_last_policy();

    float4 oa = __ldcs(o4 + 3 * t + 0);
    float4 ob = __ldcs(o4 + 3 * t + 1);
    float4 oc = __ldcs(o4 + 3 * t + 2);
    float4 va = __ldcs(v4 + 3 * t + 0);
    float4 vb = __ldcs(v4 + 3 * t + 1);
    float4 vc = __ldcs(v4 + 3 * t + 2);

    int idx0 = ray_index(oa.x, oa.y, oa.z, va.x, va.y, va.z);
    int idx1 = ray_index(oa.w, ob.x, ob.y, va.w, vb.x, vb.y);
    int idx2 = ray_index(ob.z, ob.w, oc.x, vb.z, vb.w, vc.x);
    int idx3 = ray_index(oc.y, oc.z, oc.w, vc.y, vc.z, vc.w);

    // One 4B gather per ray, MLP=4, evict_last keeps table lines hot.
    float r0, r1, r2, r3;
    asm volatile("ld.global.L2::cache_hint.f32 %0, [%1], %2;"
                 : "=f"(r0) : "l"(g_ratio + idx0), "l"(pol));
    asm volatile("ld.global.L2::cache_hint.f32 %0, [%1], %2;"
                 : "=f"(r1) : "l"(g_ratio + idx1), "l"(pol));
    asm volatile("ld.global.L2::cache_hint.f32 %0, [%1], %2;"
                 : "=f"(r2) : "l"(g_ratio + idx2), "l"(pol));
    asm volatile("ld.global.L2::cache_hint.f32 %0, [%1], %2;"
                 : "=f"(r3) : "l"(g_ratio + idx3), "l"(pol));

    float4 r = make_float4(r0, r1, r2, r3);
    __stcs(out + t, r);
}

__global__ void __launch_bounds__(256)
vis_cache_tail(const float* __restrict__ origins,
               const float* __restrict__ dirs,
               float*       __restrict__ out,
               int start, int nrays) {
    int r = start + blockIdx.x * blockDim.x + threadIdx.x;
    if (r >= nrays) return;
    int idx = ray_index(origins[3 * r], origins[3 * r + 1], origins[3 * r + 2],
                        dirs[3 * r],    dirs[3 * r + 1],    dirs[3 * r + 2]);
    out[r] = g_ratio[idx];
}

extern "C" void kernel_launch(void* const* d_in, const int* in_sizes, int n_in,
                              void* d_out, int out_size) {
    const float* origins = (const float*)d_in[0];  // [B,3] f32
    const float* dirs    = (const float*)d_in[1];  // [B,3] f32
    const int*   numer   = (const int*)d_in[2];    // [128,128,128,6] i32
    const int*   denom   = (const int*)d_in[3];    // [128,128,128,6] i32
    float* out = (float*)d_out;

    // Phase 1: fuse (TABLE_N divisible by 4)
    {
        int nvec = TABLE_N / 4;
        fuse_ratio_kernel<<<(nvec + 255) / 256, 256>>>(
            (const int4*)numer, (const int4*)denom, nvec);
    }

    // Phase 2: gather
    int nrays  = in_sizes[0] / 3;
    int nquads = nrays >> 2;
    if (nquads > 0) {
        vis_cache_kernel<<<(nquads + 255) / 256, 256>>>(
            (const float4*)origins, (const float4*)dirs, (float4*)out, nquads);
    }
    int tail_start = nquads << 2;
    int tail = nrays - tail_start;
    if (tail > 0) {
        vis_cache_tail<<<(tail + 255) / 256, 256>>>(
            origins, dirs, out, tail_start, nrays);
    }
}